// round 2
// baseline (speedup 1.0000x reference)
#include <cuda_runtime.h>
#include <cuda_bf16.h>

// Problem constants
#define NMASK 100
#define C_DIM 256
#define HDIM  128
#define WDIM  128
#define HW    16384      // 128*128
#define KCONV 2304       // 256*9
#define NROWS 800        // B*NMASK
#define POOL_KSPLIT 32   // K chunk = 16384/32 = 512

// Scratch (static device globals; allocation-free at launch time)
__device__ float g_wT[KCONV * 128];                    // conv weights, [k][m] padded to 128
__device__ float g_prob[(size_t)NROWS * HW];           // softmax probs (52.4 MB)
__device__ float g_part[POOL_KSPLIT * NROWS * C_DIM];  // pooling K-split partials (26.2 MB)
__device__ float g_inst2[NROWS * C_DIM];               // relu(fc) output
__device__ float g_fcT[C_DIM * C_DIM];                 // fc_w transposed [c][j]
__device__ float g_mkT[C_DIM * 128];                   // mk_w transposed [c][j]

// ---------------- packed-fp32 helpers (sm_103a FFMA2 path) ----------------
__device__ __forceinline__ unsigned long long pack2(float x) {
    unsigned long long r;
    unsigned u = __float_as_uint(x);
    asm("mov.b64 %0, {%1, %1};" : "=l"(r) : "r"(u));
    return r;
}
__device__ __forceinline__ void ffma2(unsigned long long& d,
                                      unsigned long long a,
                                      unsigned long long b) {
    asm("fma.rn.f32x2 %0, %1, %2, %0;" : "+l"(d) : "l"(a), "l"(b));
}

// ---------------- prep: weight transposes ----------------
__global__ void prep_kernel(const float* __restrict__ conv_w,
                            const float* __restrict__ fc_w,
                            const float* __restrict__ mk_w) {
    int i = blockIdx.x * 256 + threadIdx.x;
    if (i < KCONV * 128) {
        int k = i >> 7, m = i & 127;
        int t = k >> 8, c = k & 255;            // k = t*256 + c
        g_wT[i] = (m < NMASK) ? conv_w[m * KCONV + c * 9 + t] : 0.f;
    }
    if (i < C_DIM * C_DIM) {                     // fcT[c][j] = fc_w[j][c]
        int c = i >> 8, j = i & 255;
        g_fcT[i] = fc_w[j * C_DIM + c];
    }
    if (i < C_DIM * 128) {                       // mkT[c][j] = mk_w[j][c]
        int c = i >> 7, j = i & 127;
        g_mkT[i] = mk_w[j * C_DIM + c];
    }
}

// ---------------- conv as implicit GEMM, 128x128x8 tile, FFMA2 micro-kernel ----
// block: (h row, batch). Computes all 100 masks x 128 w positions for one row.
__global__ __launch_bounds__(256, 2)
void conv_kernel(const float* __restrict__ feat,
                 const float* __restrict__ conv_b,
                 float* __restrict__ iam_out) {
    const int h = blockIdx.x;
    const int b = blockIdx.y;
    __shared__ float As[8][128];   // As[k][m]
    __shared__ float Bs[8][128];   // Bs[k][w]
    const int tid  = threadIdx.x;
    const int trow = tid >> 4;     // m-group 0..15
    const int tcol = tid & 15;     // w-group 0..15
    const float* fb = feat + ((size_t)b << 22);   // b * 256 * 16384

    unsigned long long acc[8][4];
#pragma unroll
    for (int i = 0; i < 8; i++)
#pragma unroll
        for (int j = 0; j < 4; j++) acc[i][j] = 0ULL;

    for (int k0 = 0; k0 < KCONV; k0 += 8) {
        const int t  = k0 >> 8;          // tap 0..8 (fixed within chunk: 256 % 8 == 0)
        const int c0 = k0 & 255;
        const int hh = h + t / 3 - 1;
        const int dx = t % 3 - 1;
        const bool hok = (hh >= 0) && (hh < HDIM);
#pragma unroll
        for (int i = 0; i < 4; i++) {    // A: 128x8, coalesced from g_wT
            int idx = tid + i * 256;
            int m = idx & 127, kk = idx >> 7;
            As[kk][m] = g_wT[(k0 + kk) * 128 + m];
        }
#pragma unroll
        for (int i = 0; i < 4; i++) {    // B: shifted feature row, zero-padded borders
            int idx = tid + i * 256;
            int j = idx & 127, kk = idx >> 7;
            int ww = j + dx;
            float v = 0.f;
            if (hok && ww >= 0 && ww < WDIM)
                v = fb[((size_t)(c0 + kk) << 14) + (hh << 7) + ww];
            Bs[kk][j] = v;
        }
        __syncthreads();
#pragma unroll
        for (int kk = 0; kk < 8; kk++) {
            float4 a0 = *(const float4*)&As[kk][trow * 8];
            float4 a1 = *(const float4*)&As[kk][trow * 8 + 4];
            unsigned long long ra[8];
            ra[0] = pack2(a0.x); ra[1] = pack2(a0.y);
            ra[2] = pack2(a0.z); ra[3] = pack2(a0.w);
            ra[4] = pack2(a1.x); ra[5] = pack2(a1.y);
            ra[6] = pack2(a1.z); ra[7] = pack2(a1.w);
            unsigned long long rb[4];
#pragma unroll
            for (int j = 0; j < 4; j++)
                rb[j] = *(const unsigned long long*)&Bs[kk][tcol * 8 + 2 * j];
#pragma unroll
            for (int i = 0; i < 8; i++)
#pragma unroll
                for (int j = 0; j < 4; j++) ffma2(acc[i][j], ra[i], rb[j]);
        }
        __syncthreads();
    }
#pragma unroll
    for (int i = 0; i < 8; i++) {
        int m = trow * 8 + i;
        if (m < NMASK) {
            float bias = conv_b[m];
            size_t base = ((size_t)(b * NMASK + m) << 14) + (h << 7) + tcol * 8;
#pragma unroll
            for (int j = 0; j < 4; j++) {
                float2 v = *reinterpret_cast<float2*>(&acc[i][j]);
                v.x += bias; v.y += bias;
                *reinterpret_cast<float2*>(&iam_out[base + 2 * j]) = v;
            }
        }
    }
}

// ---------------- softmax over HW per (b,n) row ----------------
// softmax_bias and conv_b are constant along the axis -> cancel; use iam directly.
__global__ __launch_bounds__(256)
void softmax_kernel(const float* __restrict__ iam) {
    const int row = blockIdx.x;          // 0..799
    const float* x = iam + ((size_t)row << 14);
    float* p = g_prob + ((size_t)row << 14);
    const int tid = threadIdx.x;
    __shared__ float red[256];

    float mx = -1e30f;
    for (int i = tid; i < HW; i += 256) mx = fmaxf(mx, x[i]);
    red[tid] = mx; __syncthreads();
    for (int s = 128; s > 0; s >>= 1) {
        if (tid < s) red[tid] = fmaxf(red[tid], red[tid + s]);
        __syncthreads();
    }
    const float M = red[0];
    __syncthreads();

    float sum = 0.f;
    for (int i = tid; i < HW; i += 256) sum += __expf(x[i] - M);
    red[tid] = sum; __syncthreads();
    for (int s = 128; s > 0; s >>= 1) {
        if (tid < s) red[tid] += red[tid + s];
        __syncthreads();
    }
    const float inv = 1.f / red[0];

    for (int i = tid; i < HW; i += 256) p[i] = __expf(x[i] - M) * inv;
}

// ---------------- pooling GEMM: inst[n][c] = sum_p prob[n][p]*feat[c][p] ------
// 128(n) x 128(c) tile, K split 32 ways -> deterministic partials into g_part.
__global__ __launch_bounds__(256, 2)
void pool_kernel(const float* __restrict__ feat) {
    const int ks = blockIdx.x;   // 0..31
    const int ct = blockIdx.y;   // 0..1  (c half)
    const int b  = blockIdx.z;   // 0..7
    __shared__ float As[8][132]; // As[k][n], padded stride (conflict-free transpose store)
    __shared__ float Bs[8][132]; // Bs[k][c]
    const int tid  = threadIdx.x;
    const int trow = tid >> 4;
    const int tcol = tid & 15;
    const int p0   = ks * (HW / POOL_KSPLIT);
    const float* fb = feat + ((size_t)b << 22);

    unsigned long long acc[8][4];
#pragma unroll
    for (int i = 0; i < 8; i++)
#pragma unroll
        for (int j = 0; j < 4; j++) acc[i][j] = 0ULL;

    for (int pp = p0; pp < p0 + (HW / POOL_KSPLIT); pp += 8) {
#pragma unroll
        for (int i = 0; i < 4; i++) {
            int idx = tid + i * 256;
            int n = idx >> 3, kk = idx & 7;
            float v = 0.f;
            if (n < NMASK)
                v = g_prob[((size_t)(b * NMASK + n) << 14) + pp + kk];
            As[kk][n] = v;
        }
#pragma unroll
        for (int i = 0; i < 4; i++) {
            int idx = tid + i * 256;
            int cc = idx >> 3, kk = idx & 7;
            int c = ct * 128 + cc;
            Bs[kk][cc] = fb[((size_t)c << 14) + pp + kk];
        }
        __syncthreads();
#pragma unroll
        for (int kk = 0; kk < 8; kk++) {
            float4 a0 = *(const float4*)&As[kk][trow * 8];
            float4 a1 = *(const float4*)&As[kk][trow * 8 + 4];
            unsigned long long ra[8];
            ra[0] = pack2(a0.x); ra[1] = pack2(a0.y);
            ra[2] = pack2(a0.z); ra[3] = pack2(a0.w);
            ra[4] = pack2(a1.x); ra[5] = pack2(a1.y);
            ra[6] = pack2(a1.z); ra[7] = pack2(a1.w);
            unsigned long long rb[4];
#pragma unroll
            for (int j = 0; j < 4; j++)
                rb[j] = *(const unsigned long long*)&Bs[kk][tcol * 8 + 2 * j];
#pragma unroll
            for (int i = 0; i < 8; i++)
#pragma unroll
                for (int j = 0; j < 4; j++) ffma2(acc[i][j], ra[i], rb[j]);
        }
        __syncthreads();
    }
#pragma unroll
    for (int i = 0; i < 8; i++) {
        int n = trow * 8 + i;
        if (n < NMASK) {
            size_t base = (size_t)ks * (NROWS * C_DIM)
                        + (size_t)(b * NMASK + n) * C_DIM + ct * 128 + tcol * 8;
#pragma unroll
            for (int j = 0; j < 4; j++) {
                float2 v = *reinterpret_cast<float2*>(&acc[i][j]);
                *reinterpret_cast<float2*>(&g_part[base + 2 * j]) = v;
            }
        }
    }
}

// ---------------- fc: inst2 = relu( (sum_k part) @ fc_w^T + fc_b ) ------------
__global__ __launch_bounds__(256)
void fc_kernel(const float* __restrict__ fc_b) {
    const int r0 = blockIdx.x * 8;   // 100 blocks x 8 rows
    __shared__ float s_in[8][C_DIM];
    const int tid = threadIdx.x;

#pragma unroll
    for (int rr = 0; rr < 8; rr++) {
        float v = 0.f;
#pragma unroll
        for (int ks = 0; ks < POOL_KSPLIT; ks++)
            v += g_part[(size_t)ks * (NROWS * C_DIM) + (r0 + rr) * C_DIM + tid];
        s_in[rr][tid] = v;
    }
    __syncthreads();

    const float bias = fc_b[tid];
    float acc[8];
#pragma unroll
    for (int rr = 0; rr < 8; rr++) acc[rr] = bias;
    for (int c = 0; c < C_DIM; c++) {
        float w = g_fcT[c * C_DIM + tid];
#pragma unroll
        for (int rr = 0; rr < 8; rr++) acc[rr] += s_in[rr][c] * w;
    }
#pragma unroll
    for (int rr = 0; rr < 8; rr++)
        g_inst2[(r0 + rr) * C_DIM + tid] = fmaxf(acc[rr], 0.f);
}

// ---------------- heads: logits / kernel / scores ----------------
__global__ __launch_bounds__(192)
void heads_kernel(float* __restrict__ out,
                  const float* __restrict__ cls_w, const float* __restrict__ cls_b,
                  const float* __restrict__ obj_w, const float* __restrict__ obj_b,
                  const float* __restrict__ mk_b) {
    const int r = blockIdx.x;   // 0..799
    __shared__ float s[C_DIM];
    const int tid = threadIdx.x;
    for (int i = tid; i < C_DIM; i += 192) s[i] = g_inst2[r * C_DIM + i];
    __syncthreads();

    if (tid < 128) {
        float a = mk_b[tid];
        for (int c = 0; c < C_DIM; c++) a += s[c] * g_mkT[c * 128 + tid];
        out[800 + r * 128 + tid] = a;                         // pred_kernel
    } else {
        const int w = (tid - 128) >> 5;    // 0 = cls, 1 = obj (full warps)
        const int lane = tid & 31;
        const float* wv = (w == 0) ? cls_w : obj_w;
        float p = 0.f;
        for (int c = lane; c < C_DIM; c += 32) p += s[c] * wv[c];
#pragma unroll
        for (int off = 16; off; off >>= 1) p += __shfl_down_sync(0xffffffff, p, off);
        if (lane == 0) {
            if (w == 0) out[r] = p + cls_b[0];                // pred_logits
            else        out[103200 + r] = p + obj_b[0];       // pred_scores
        }
    }
}

// ---------------- launch ----------------
// d_out layout (float): [0,800) pred_logits | [800,103200) pred_kernel
//                       | [103200,104000) pred_scores | [104000, ...) iam
extern "C" void kernel_launch(void* const* d_in, const int* in_sizes, int n_in,
                              void* d_out, int out_size) {
    const float* features = (const float*)d_in[0];
    const float* conv_w   = (const float*)d_in[1];
    const float* conv_b   = (const float*)d_in[2];
    // d_in[3] = softmax_bias: constant along softmax axis -> cancels, unused
    const float* fc_w     = (const float*)d_in[4];
    const float* fc_b     = (const float*)d_in[5];
    const float* cls_w    = (const float*)d_in[6];
    const float* cls_b    = (const float*)d_in[7];
    const float* mk_w     = (const float*)d_in[8];
    const float* mk_b     = (const float*)d_in[9];
    const float* obj_w    = (const float*)d_in[10];
    const float* obj_b    = (const float*)d_in[11];
    float* out = (float*)d_out;
    float* iam = out + 104000;

    prep_kernel<<<1152, 256>>>(conv_w, fc_w, mk_w);
    conv_kernel<<<dim3(HDIM, 8), 256>>>(features, conv_b, iam);
    softmax_kernel<<<NROWS, 256>>>(iam);
    pool_kernel<<<dim3(POOL_KSPLIT, 2, 8), 256>>>(features);
    fc_kernel<<<100, 256>>>(fc_b);
    heads_kernel<<<NROWS, 192>>>(out, cls_w, cls_b, obj_w, obj_b, mk_b);
}

// round 15
// speedup vs baseline: 2.1547x; 2.1547x over previous
#include <cuda_runtime.h>
#include <cuda_bf16.h>
#include <cstdint>

// Problem constants
#define NMASK 100
#define C_DIM 256
#define HDIM  128
#define WDIM  128
#define HW    16384
#define KCONV 2304
#define NROWS 800
#define POOL_KSPLIT 32

#define NCHUNK  36        // 2304 / 64
#define CHUNK_K 64

// ---------------- global scratch ----------------
__device__ __nv_bfloat16 g_wA_hi[NCHUNK * 8192];   // pre-swizzled weight tiles (hi)
__device__ __nv_bfloat16 g_wA_lo[NCHUNK * 8192];   // pre-swizzled weight tiles (lo)
__device__ __nv_bfloat16 g_fThi[(size_t)8 * HW * C_DIM];  // feat transposed [b][p][c] hi
__device__ __nv_bfloat16 g_fTlo[(size_t)8 * HW * C_DIM];  // feat transposed [b][p][c] lo
__device__ float g_prob[(size_t)NROWS * HW];
__device__ float g_part[POOL_KSPLIT * NROWS * C_DIM];
__device__ float g_inst2[NROWS * C_DIM];
__device__ float g_fcT[C_DIM * C_DIM];
__device__ float g_mkT[C_DIM * 128];

// ---------------- helpers ----------------
__device__ __forceinline__ uint32_t smem_u32(const void* p) {
    uint32_t a;
    asm("{ .reg .u64 t; cvta.to.shared.u64 t, %1; cvt.u32.u64 %0, t; }"
        : "=r"(a) : "l"(p));
    return a;
}
#define SWZ128(off) ((off) ^ (((off) >> 3) & 0x70))

// ldmatrix x4 (sm_75+; plain-target safe)
__device__ __forceinline__ void ldsm_x4(uint32_t* r, uint32_t addr) {
    asm volatile("ldmatrix.sync.aligned.m8n8.x4.shared.b16 {%0,%1,%2,%3}, [%4];"
        : "=r"(r[0]), "=r"(r[1]), "=r"(r[2]), "=r"(r[3]) : "r"(addr));
}
// bf16 mma m16n8k16 (sm_80+; plain-target safe)
__device__ __forceinline__ void mma_bf16(float* c, const uint32_t* a, const uint32_t* b) {
    asm volatile("mma.sync.aligned.m16n8k16.row.col.f32.bf16.bf16.f32 "
        "{%0,%1,%2,%3}, {%4,%5,%6,%7}, {%8,%9}, {%0,%1,%2,%3};"
        : "+f"(c[0]), "+f"(c[1]), "+f"(c[2]), "+f"(c[3])
        : "r"(a[0]), "r"(a[1]), "r"(a[2]), "r"(a[3]), "r"(b[0]), "r"(b[1]));
}

// ---------------- packed-fp32 helpers (pool/fc path) ----------------
__device__ __forceinline__ unsigned long long pack2(float x) {
    unsigned long long r;
    unsigned u = __float_as_uint(x);
    asm("mov.b64 %0, {%1, %1};" : "=l"(r) : "r"(u));
    return r;
}
__device__ __forceinline__ void ffma2(unsigned long long& d,
                                      unsigned long long a,
                                      unsigned long long b) {
    asm("fma.rn.f32x2 %0, %1, %2, %0;" : "+l"(d) : "l"(a), "l"(b));
}

// ---------------- prep: weight split + pre-swizzle; fc/mk transposes ----------
__global__ void prep_w_kernel(const float* __restrict__ conv_w,
                              const float* __restrict__ fc_w,
                              const float* __restrict__ mk_w) {
    int i = blockIdx.x * 256 + threadIdx.x;
    if (i < NCHUNK * 8192) {
        int q = i >> 13, r = i & 8191;
        int m = r >> 6, kk = r & 63;
        int k = q * CHUNK_K + kk;
        int t = k >> 8, c = k & 255;
        float v = (m < NMASK) ? conv_w[m * KCONV + c * 9 + t] : 0.f;
        __nv_bfloat16 hi = __float2bfloat16(v);
        __nv_bfloat16 lo = __float2bfloat16(v - __bfloat162float(hi));
        uint32_t swz = SWZ128((uint32_t)(m * 128 + kk * 2));
        g_wA_hi[q * 8192 + (swz >> 1)] = hi;
        g_wA_lo[q * 8192 + (swz >> 1)] = lo;
    }
    if (i < C_DIM * C_DIM) {
        int c = i >> 8, j = i & 255;
        g_fcT[i] = fc_w[j * C_DIM + c];
    }
    if (i < C_DIM * 128) {
        int c = i >> 7, j = i & 127;
        g_mkT[i] = mk_w[j * C_DIM + c];
    }
}

// ---------------- prep: feature split + transpose to [b][p][c] bf16 -----------
__global__ __launch_bounds__(256)
void prep_feat_kernel(const float* __restrict__ feat) {
    __shared__ __nv_bfloat16 sh_hi[64][66];
    __shared__ __nv_bfloat16 sh_lo[64][66];
    const int p0 = blockIdx.x * 64;
    const int c0 = blockIdx.y * 64;
    const int b  = blockIdx.z;
    const float* fb = feat + ((size_t)b << 22);
#pragma unroll
    for (int i = 0; i < 16; i++) {
        int idx = threadIdx.x + i * 256;
        int ci = idx >> 6, pj = idx & 63;
        float v = fb[((size_t)(c0 + ci) << 14) + p0 + pj];
        __nv_bfloat16 hi = __float2bfloat16(v);
        __nv_bfloat16 lo = __float2bfloat16(v - __bfloat162float(hi));
        sh_hi[ci][pj] = hi;
        sh_lo[ci][pj] = lo;
    }
    __syncthreads();
    const size_t obase = ((size_t)b << 14) * C_DIM;
#pragma unroll
    for (int i = 0; i < 16; i++) {
        int idx = threadIdx.x + i * 256;
        int pi = idx >> 6, cj = idx & 63;
        size_t o = obase + (size_t)(p0 + pi) * C_DIM + c0 + cj;
        g_fThi[o] = sh_hi[cj][pi];
        g_fTlo[o] = sh_lo[cj][pi];
    }
}

// ---------------- conv via ldmatrix + mma.sync bf16-split implicit GEMM -------
// grid (128 h, 8 b). 256 thr = 8 warps, warp tile m32 x n64 (4x2 warp grid).
// SMEM (1024-aligned): Ah[16K] Al[16K] Bh[16K] Bl[16K] = 64KB, single stage.
#define CONV_SMEM (1024 + 4 * 16384)

__global__ __launch_bounds__(256, 2)
void conv_mma_kernel(const float* __restrict__ conv_b,
                     float* __restrict__ iam_out) {
    extern __shared__ char smem[];
    const uint32_t sb = smem_u32(smem);
    const uint32_t tile0 = (sb + 1023) & ~1023u;
    char* tb = smem + (tile0 - sb);
    const uint32_t Ah = tile0, Al = tile0 + 16384, Bh = tile0 + 32768, Bl = tile0 + 49152;

    const int h = blockIdx.x, b = blockIdx.y;
    const int tid = threadIdx.x;
    const int wid = tid >> 5, lane = tid & 31;
    const int wm = wid >> 1, wn = wid & 1;     // warp tile: rows wm*32, cols wn*64

    // ldmatrix lane->address components (fixed per lane)
    const int lmat = lane >> 3, lrow = lane & 7;
    // A x4 for m16 tile i: m = wm*32 + i*16 + (lmat&1)*8 + lrow ; k-chunk half = lmat>>1
    const uint32_t a_row0 = (uint32_t)((wm * 32 + (lmat & 1) * 8 + lrow) * 128);
    const uint32_t a_kb   = (uint32_t)((lmat >> 1) * 16);
    // B x4 for n8-tile pair t: n = wn*64 + (2t + (lmat>>1))*8 + lrow ; k half = lmat&1
    const uint32_t b_row0 = (uint32_t)((wn * 64 + (lmat >> 1) * 8 + lrow) * 128);
    const uint32_t b_kb   = (uint32_t)((lmat & 1) * 16);

    const __nv_bfloat16* fThi = g_fThi + ((size_t)b << 14) * C_DIM;
    const __nv_bfloat16* fTlo = g_fTlo + ((size_t)b << 14) * C_DIM;

    float acc[2][8][4];
#pragma unroll
    for (int i = 0; i < 2; i++)
#pragma unroll
        for (int j = 0; j < 8; j++)
#pragma unroll
            for (int v = 0; v < 4; v++) acc[i][j][v] = 0.f;

    for (int q = 0; q < NCHUNK; q++) {
        // ---- fill A: linear 16KB copies of pre-swizzled weights ----
        const uint4* sAh = (const uint4*)(g_wA_hi + q * 8192);
        const uint4* sAl = (const uint4*)(g_wA_lo + q * 8192);
#pragma unroll
        for (int i = 0; i < 4; i++) {
            int idx = tid + i * 256;
            ((uint4*)tb)[idx]            = sAh[idx];
            ((uint4*)(tb + 16384))[idx]  = sAl[idx];
        }
        // ---- fill B: 128 n-rows x 64 channels, shifted features, swizzled ----
        const int t  = q >> 2;
        const int c0 = (q & 3) * CHUNK_K;
        const int hh = h + t / 3 - 1;
        const int dx = t % 3 - 1;
        const bool hok = (hh >= 0) && (hh < HDIM);
#pragma unroll
        for (int i = 0; i < 4; i++) {
            int idx = tid + i * 256;          // 0..1023
            int n = idx >> 3, g = idx & 7;
            uint4 vh = make_uint4(0, 0, 0, 0), vl = make_uint4(0, 0, 0, 0);
            if (hok && (unsigned)(n + dx) < (unsigned)WDIM) {
                size_t off = (size_t)(hh * WDIM + n + dx) * C_DIM + c0 + g * 8;
                vh = *(const uint4*)(fThi + off);
                vl = *(const uint4*)(fTlo + off);
            }
            uint32_t so = SWZ128((uint32_t)(n * 128 + g * 16));
            *(uint4*)(tb + 32768 + so) = vh;
            *(uint4*)(tb + 49152 + so) = vl;
        }
        __syncthreads();

        // ---- compute: 4 k16 steps ----
#pragma unroll
        for (int kc = 0; kc < CHUNK_K; kc += 16) {
            uint32_t ah[2][4], al[2][4];
#pragma unroll
            for (int i = 0; i < 2; i++) {
                uint32_t off = a_row0 + (uint32_t)(i * 16 * 128) + (uint32_t)(kc * 2) + a_kb;
                ldsm_x4(ah[i], Ah + SWZ128(off));
                ldsm_x4(al[i], Al + SWZ128(off));
            }
#pragma unroll
            for (int tt = 0; tt < 4; tt++) {   // pairs of n8 tiles
                uint32_t bh[4], bl[4];
                uint32_t off = b_row0 + (uint32_t)(tt * 16 * 128) + (uint32_t)(kc * 2) + b_kb;
                ldsm_x4(bh, Bh + SWZ128(off));
                ldsm_x4(bl, Bl + SWZ128(off));
#pragma unroll
                for (int i = 0; i < 2; i++) {
                    mma_bf16(acc[i][2 * tt],     ah[i], bh);       // hi*hi (n8 tile even)
                    mma_bf16(acc[i][2 * tt + 1], ah[i], bh + 2);   // hi*hi (odd)
                    mma_bf16(acc[i][2 * tt],     al[i], bh);       // lo*hi
                    mma_bf16(acc[i][2 * tt + 1], al[i], bh + 2);
                    mma_bf16(acc[i][2 * tt],     ah[i], bl);       // hi*lo
                    mma_bf16(acc[i][2 * tt + 1], ah[i], bl + 2);
                }
            }
        }
        __syncthreads();
    }

    // ---- epilogue: registers -> gmem, + bias; skip m >= NMASK ----
    const int col0 = wn * 64 + (lane & 3) * 2;
    const int rbase = wm * 32 + (lane >> 2);
#pragma unroll
    for (int i = 0; i < 2; i++) {
        int m0 = rbase + i * 16;
#pragma unroll
        for (int half = 0; half < 2; half++) {
            int m = m0 + half * 8;
            if (m < NMASK) {
                float bias = conv_b[m];
                size_t base = ((size_t)(b * NMASK + m) << 14) + (h << 7);
#pragma unroll
                for (int j = 0; j < 8; j++) {
                    float2 v;
                    v.x = acc[i][j][half * 2 + 0] + bias;
                    v.y = acc[i][j][half * 2 + 1] + bias;
                    *(float2*)&iam_out[base + col0 + j * 8] = v;
                }
            }
        }
    }
}

// ---------------- softmax over HW per (b,n) row ----------------
__global__ __launch_bounds__(256)
void softmax_kernel(const float* __restrict__ iam) {
    const int row = blockIdx.x;
    const float* x = iam + ((size_t)row << 14);
    float* p = g_prob + ((size_t)row << 14);
    const int tid = threadIdx.x;
    __shared__ float red[256];

    float mx = -1e30f;
    for (int i = tid; i < HW; i += 256) mx = fmaxf(mx, x[i]);
    red[tid] = mx; __syncthreads();
    for (int s = 128; s > 0; s >>= 1) {
        if (tid < s) red[tid] = fmaxf(red[tid], red[tid + s]);
        __syncthreads();
    }
    const float M = red[0];
    __syncthreads();

    float sum = 0.f;
    for (int i = tid; i < HW; i += 256) sum += __expf(x[i] - M);
    red[tid] = sum; __syncthreads();
    for (int s = 128; s > 0; s >>= 1) {
        if (tid < s) red[tid] += red[tid + s];
        __syncthreads();
    }
    const float inv = 1.f / red[0];

    for (int i = tid; i < HW; i += 256) p[i] = __expf(x[i] - M) * inv;
}

// ---------------- pooling GEMM (FFMA2), K split 32 ways ----------------
__global__ __launch_bounds__(256, 2)
void pool_kernel(const float* __restrict__ feat) {
    const int ks = blockIdx.x;
    const int ct = blockIdx.y;
    const int b  = blockIdx.z;
    __shared__ float As[8][132];
    __shared__ float Bs[8][132];
    const int tid  = threadIdx.x;
    const int trow = tid >> 4;
    const int tcol = tid & 15;
    const int p0   = ks * (HW / POOL_KSPLIT);
    const float* fb = feat + ((size_t)b << 22);

    unsigned long long acc[8][4];
#pragma unroll
    for (int i = 0; i < 8; i++)
#pragma unroll
        for (int j = 0; j < 4; j++) acc[i][j] = 0ULL;

    for (int pp = p0; pp < p0 + (HW / POOL_KSPLIT); pp += 8) {
#pragma unroll
        for (int i = 0; i < 4; i++) {
            int idx = tid + i * 256;
            int n = idx >> 3, kk = idx & 7;
            float v = 0.f;
            if (n < NMASK)
                v = g_prob[((size_t)(b * NMASK + n) << 14) + pp + kk];
            As[kk][n] = v;
        }
#pragma unroll
        for (int i = 0; i < 4; i++) {
            int idx = tid + i * 256;
            int cc = idx >> 3, kk = idx & 7;
            int c = ct * 128 + cc;
            Bs[kk][cc] = fb[((size_t)c << 14) + pp + kk];
        }
        __syncthreads();
#pragma unroll
        for (int kk = 0; kk < 8; kk++) {
            float4 a0 = *(const float4*)&As[kk][trow * 8];
            float4 a1 = *(const float4*)&As[kk][trow * 8 + 4];
            unsigned long long ra[8];
            ra[0] = pack2(a0.x); ra[1] = pack2(a0.y);
            ra[2] = pack2(a0.z); ra[3] = pack2(a0.w);
            ra[4] = pack2(a1.x); ra[5] = pack2(a1.y);
            ra[6] = pack2(a1.z); ra[7] = pack2(a1.w);
            unsigned long long rb[4];
#pragma unroll
            for (int j = 0; j < 4; j++)
                rb[j] = *(const unsigned long long*)&Bs[kk][tcol * 8 + 2 * j];
#pragma unroll
            for (int i = 0; i < 8; i++)
#pragma unroll
                for (int j = 0; j < 4; j++) ffma2(acc[i][j], ra[i], rb[j]);
        }
        __syncthreads();
    }
#pragma unroll
    for (int i = 0; i < 8; i++) {
        int n = trow * 8 + i;
        if (n < NMASK) {
            size_t base = (size_t)ks * (NROWS * C_DIM)
                        + (size_t)(b * NMASK + n) * C_DIM + ct * 128 + tcol * 8;
#pragma unroll
            for (int j = 0; j < 4; j++) {
                float2 v = *reinterpret_cast<float2*>(&acc[i][j]);
                *reinterpret_cast<float2*>(&g_part[base + 2 * j]) = v;
            }
        }
    }
}

// ---------------- fc: inst2 = relu( (sum_k part) @ fc_w^T + fc_b ) ------------
__global__ __launch_bounds__(256)
void fc_kernel(const float* __restrict__ fc_b) {
    const int r0 = blockIdx.x * 8;
    __shared__ float s_in[8][C_DIM];
    const int tid = threadIdx.x;

#pragma unroll
    for (int rr = 0; rr < 8; rr++) {
        float v = 0.f;
#pragma unroll
        for (int ks = 0; ks < POOL_KSPLIT; ks++)
            v += g_part[(size_t)ks * (NROWS * C_DIM) + (r0 + rr) * C_DIM + tid];
        s_in[rr][tid] = v;
    }
    __syncthreads();

    const float bias = fc_b[tid];
    float acc[8];
#pragma unroll
    for (int rr = 0; rr < 8; rr++) acc[rr] = bias;
    for (int c = 0; c < C_DIM; c++) {
        float w = g_fcT[c * C_DIM + tid];
#pragma unroll
        for (int rr = 0; rr < 8; rr++) acc[rr] += s_in[rr][c] * w;
    }
#pragma unroll
    for (int rr = 0; rr < 8; rr++)
        g_inst2[(r0 + rr) * C_DIM + tid] = fmaxf(acc[rr], 0.f);
}

// ---------------- heads ----------------
__global__ __launch_bounds__(192)
void heads_kernel(float* __restrict__ out,
                  const float* __restrict__ cls_w, const float* __restrict__ cls_b,
                  const float* __restrict__ obj_w, const float* __restrict__ obj_b,
                  const float* __restrict__ mk_b) {
    const int r = blockIdx.x;
    __shared__ float s[C_DIM];
    const int tid = threadIdx.x;
    for (int i = tid; i < C_DIM; i += 192) s[i] = g_inst2[r * C_DIM + i];
    __syncthreads();

    if (tid < 128) {
        float a = mk_b[tid];
        for (int c = 0; c < C_DIM; c++) a += s[c] * g_mkT[c * 128 + tid];
        out[800 + r * 128 + tid] = a;
    } else {
        const int w = (tid - 128) >> 5;
        const int lane = tid & 31;
        const float* wv = (w == 0) ? cls_w : obj_w;
        float p = 0.f;
        for (int c = lane; c < C_DIM; c += 32) p += s[c] * wv[c];
#pragma unroll
        for (int off = 16; off; off >>= 1) p += __shfl_down_sync(0xffffffff, p, off);
        if (lane == 0) {
            if (w == 0) out[r] = p + cls_b[0];
            else        out[103200 + r] = p + obj_b[0];
        }
    }
}

// ---------------- launch ----------------
// d_out layout (float): [0,800) pred_logits | [800,103200) pred_kernel
//                       | [103200,104000) pred_scores | [104000, ...) iam
extern "C" void kernel_launch(void* const* d_in, const int* in_sizes, int n_in,
                              void* d_out, int out_size) {
    const float* features = (const float*)d_in[0];
    const float* conv_w   = (const float*)d_in[1];
    const float* conv_b   = (const float*)d_in[2];
    const float* fc_w     = (const float*)d_in[4];
    const float* fc_b     = (const float*)d_in[5];
    const float* cls_w    = (const float*)d_in[6];
    const float* cls_b    = (const float*)d_in[7];
    const float* mk_w     = (const float*)d_in[8];
    const float* mk_b     = (const float*)d_in[9];
    const float* obj_w    = (const float*)d_in[10];
    const float* obj_b    = (const float*)d_in[11];
    float* out = (float*)d_out;
    float* iam = out + 104000;

    cudaFuncSetAttribute(conv_mma_kernel,
                         cudaFuncAttributeMaxDynamicSharedMemorySize, CONV_SMEM);

    prep_w_kernel<<<1152, 256>>>(conv_w, fc_w, mk_w);
    prep_feat_kernel<<<dim3(256, 4, 8), 256>>>(features);
    conv_mma_kernel<<<dim3(HDIM, 8), 256, CONV_SMEM>>>(conv_b, iam);
    softmax_kernel<<<NROWS, 256>>>(iam);
    pool_kernel<<<dim3(POOL_KSPLIT, 2, 8), 256>>>(features);
    fc_kernel<<<100, 256>>>(fc_b);
    heads_kernel<<<NROWS, 192>>>(out, cls_w, cls_b, obj_w, obj_b, mk_b);
}

// round 17
// speedup vs baseline: 2.4805x; 1.1512x over previous
#include <cuda_runtime.h>
#include <cuda_bf16.h>
#include <cstdint>

// Problem constants
#define NMASK 100
#define C_DIM 256
#define HDIM  128
#define WDIM  128
#define HW    16384
#define KCONV 2304
#define NROWS 800
#define POOL_KSPLIT 32

#define NCHUNK  36        // 2304 / 64
#define CHUNK_K 64

// ---------------- global scratch ----------------
__device__ __nv_bfloat16 g_wA_hi[NCHUNK * 8192];   // pre-swizzled weight tiles (hi)
__device__ __nv_bfloat16 g_wA_lo[NCHUNK * 8192];   // pre-swizzled weight tiles (lo)
__device__ __nv_bfloat16 g_fThi[(size_t)8 * HW * C_DIM];  // feat transposed [b][p][c] hi
__device__ __nv_bfloat16 g_fTlo[(size_t)8 * HW * C_DIM];  // feat transposed [b][p][c] lo
__device__ __nv_bfloat16 g_fChi[(size_t)8 * C_DIM * HW];  // feat [b][c][p] hi (pool B)
__device__ __nv_bfloat16 g_fClo[(size_t)8 * C_DIM * HW];  // feat [b][c][p] lo
__device__ __nv_bfloat16 g_phi[(size_t)NROWS * HW];       // prob hi (pool A)
__device__ __nv_bfloat16 g_plo[(size_t)NROWS * HW];       // prob lo
__device__ float g_part[POOL_KSPLIT * NROWS * C_DIM];
__device__ float g_inst2[NROWS * C_DIM];
__device__ float g_fcT[C_DIM * C_DIM];
__device__ float g_mkT[C_DIM * 128];

// ---------------- helpers ----------------
__device__ __forceinline__ uint32_t smem_u32(const void* p) {
    uint32_t a;
    asm("{ .reg .u64 t; cvta.to.shared.u64 t, %1; cvt.u32.u64 %0, t; }"
        : "=r"(a) : "l"(p));
    return a;
}
#define SWZ128(off) ((off) ^ (((off) >> 3) & 0x70))

// ldmatrix x4 (sm_75+; plain-target safe)
__device__ __forceinline__ void ldsm_x4(uint32_t* r, uint32_t addr) {
    asm volatile("ldmatrix.sync.aligned.m8n8.x4.shared.b16 {%0,%1,%2,%3}, [%4];"
        : "=r"(r[0]), "=r"(r[1]), "=r"(r[2]), "=r"(r[3]) : "r"(addr));
}
// bf16 mma m16n8k16 (sm_80+; plain-target safe)
__device__ __forceinline__ void mma_bf16(float* c, const uint32_t* a, const uint32_t* b) {
    asm volatile("mma.sync.aligned.m16n8k16.row.col.f32.bf16.bf16.f32 "
        "{%0,%1,%2,%3}, {%4,%5,%6,%7}, {%8,%9}, {%0,%1,%2,%3};"
        : "+f"(c[0]), "+f"(c[1]), "+f"(c[2]), "+f"(c[3])
        : "r"(a[0]), "r"(a[1]), "r"(a[2]), "r"(a[3]), "r"(b[0]), "r"(b[1]));
}

// ---------------- prep: weight split + pre-swizzle; fc/mk transposes ----------
__global__ void prep_w_kernel(const float* __restrict__ conv_w,
                              const float* __restrict__ fc_w,
                              const float* __restrict__ mk_w) {
    int i = blockIdx.x * 256 + threadIdx.x;
    if (i < NCHUNK * 8192) {
        int q = i >> 13, r = i & 8191;
        int m = r >> 6, kk = r & 63;
        int k = q * CHUNK_K + kk;
        int t = k >> 8, c = k & 255;
        float v = (m < NMASK) ? conv_w[m * KCONV + c * 9 + t] : 0.f;
        __nv_bfloat16 hi = __float2bfloat16(v);
        __nv_bfloat16 lo = __float2bfloat16(v - __bfloat162float(hi));
        uint32_t swz = SWZ128((uint32_t)(m * 128 + kk * 2));
        g_wA_hi[q * 8192 + (swz >> 1)] = hi;
        g_wA_lo[q * 8192 + (swz >> 1)] = lo;
    }
    if (i < C_DIM * C_DIM) {
        int c = i >> 8, j = i & 255;
        g_fcT[i] = fc_w[j * C_DIM + c];
    }
    if (i < C_DIM * 128) {
        int c = i >> 7, j = i & 127;
        g_mkT[i] = mk_w[j * C_DIM + c];
    }
}

// ---------------- prep: feature split; transposed [b][p][c] + direct [b][c][p] -
__global__ __launch_bounds__(256)
void prep_feat_kernel(const float* __restrict__ feat) {
    __shared__ __nv_bfloat16 sh_hi[64][66];
    __shared__ __nv_bfloat16 sh_lo[64][66];
    const int p0 = blockIdx.x * 64;
    const int c0 = blockIdx.y * 64;
    const int b  = blockIdx.z;
    const float* fb = feat + ((size_t)b << 22);
    const size_t cbase = ((size_t)b * C_DIM) * HW;
#pragma unroll
    for (int i = 0; i < 16; i++) {
        int idx = threadIdx.x + i * 256;
        int ci = idx >> 6, pj = idx & 63;
        float v = fb[((size_t)(c0 + ci) << 14) + p0 + pj];
        __nv_bfloat16 hi = __float2bfloat16(v);
        __nv_bfloat16 lo = __float2bfloat16(v - __bfloat162float(hi));
        sh_hi[ci][pj] = hi;
        sh_lo[ci][pj] = lo;
        size_t oc = cbase + (size_t)(c0 + ci) * HW + p0 + pj;   // [b][c][p]
        g_fChi[oc] = hi;
        g_fClo[oc] = lo;
    }
    __syncthreads();
    const size_t obase = ((size_t)b << 14) * C_DIM;
#pragma unroll
    for (int i = 0; i < 16; i++) {
        int idx = threadIdx.x + i * 256;
        int pi = idx >> 6, cj = idx & 63;
        size_t o = obase + (size_t)(p0 + pi) * C_DIM + c0 + cj;
        g_fThi[o] = sh_hi[cj][pi];
        g_fTlo[o] = sh_lo[cj][pi];
    }
}

// ---------------- conv via ldmatrix + mma.sync bf16-split implicit GEMM -------
// grid (128 h, 8 b). 256 thr = 8 warps, warp tile m32 x n64 (4x2 warp grid).
// SMEM (1024-aligned): Ah[16K] Al[16K] Bh[16K] Bl[16K] = 64KB, single stage.
#define CONV_SMEM (1024 + 4 * 16384)

__global__ __launch_bounds__(256, 2)
void conv_mma_kernel(const float* __restrict__ conv_b,
                     float* __restrict__ iam_out) {
    extern __shared__ char smem[];
    const uint32_t sb = smem_u32(smem);
    const uint32_t tile0 = (sb + 1023) & ~1023u;
    char* tb = smem + (tile0 - sb);
    const uint32_t Ah = tile0, Al = tile0 + 16384, Bh = tile0 + 32768, Bl = tile0 + 49152;

    const int h = blockIdx.x, b = blockIdx.y;
    const int tid = threadIdx.x;
    const int wid = tid >> 5, lane = tid & 31;
    const int wm = wid >> 1, wn = wid & 1;

    const int lmat = lane >> 3, lrow = lane & 7;
    const uint32_t a_row0 = (uint32_t)((wm * 32 + (lmat & 1) * 8 + lrow) * 128);
    const uint32_t a_kb   = (uint32_t)((lmat >> 1) * 16);
    const uint32_t b_row0 = (uint32_t)((wn * 64 + (lmat >> 1) * 8 + lrow) * 128);
    const uint32_t b_kb   = (uint32_t)((lmat & 1) * 16);

    const __nv_bfloat16* fThi = g_fThi + ((size_t)b << 14) * C_DIM;
    const __nv_bfloat16* fTlo = g_fTlo + ((size_t)b << 14) * C_DIM;

    float acc[2][8][4];
#pragma unroll
    for (int i = 0; i < 2; i++)
#pragma unroll
        for (int j = 0; j < 8; j++)
#pragma unroll
            for (int v = 0; v < 4; v++) acc[i][j][v] = 0.f;

    for (int q = 0; q < NCHUNK; q++) {
        const uint4* sAh = (const uint4*)(g_wA_hi + q * 8192);
        const uint4* sAl = (const uint4*)(g_wA_lo + q * 8192);
#pragma unroll
        for (int i = 0; i < 4; i++) {
            int idx = tid + i * 256;
            ((uint4*)tb)[idx]            = sAh[idx];
            ((uint4*)(tb + 16384))[idx]  = sAl[idx];
        }
        const int t  = q >> 2;
        const int c0 = (q & 3) * CHUNK_K;
        const int hh = h + t / 3 - 1;
        const int dx = t % 3 - 1;
        const bool hok = (hh >= 0) && (hh < HDIM);
#pragma unroll
        for (int i = 0; i < 4; i++) {
            int idx = tid + i * 256;
            int n = idx >> 3, g = idx & 7;
            uint4 vh = make_uint4(0, 0, 0, 0), vl = make_uint4(0, 0, 0, 0);
            if (hok && (unsigned)(n + dx) < (unsigned)WDIM) {
                size_t off = (size_t)(hh * WDIM + n + dx) * C_DIM + c0 + g * 8;
                vh = *(const uint4*)(fThi + off);
                vl = *(const uint4*)(fTlo + off);
            }
            uint32_t so = SWZ128((uint32_t)(n * 128 + g * 16));
            *(uint4*)(tb + 32768 + so) = vh;
            *(uint4*)(tb + 49152 + so) = vl;
        }
        __syncthreads();

#pragma unroll
        for (int kc = 0; kc < CHUNK_K; kc += 16) {
            uint32_t ah[2][4], al[2][4];
#pragma unroll
            for (int i = 0; i < 2; i++) {
                uint32_t off = a_row0 + (uint32_t)(i * 16 * 128) + (uint32_t)(kc * 2) + a_kb;
                ldsm_x4(ah[i], Ah + SWZ128(off));
                ldsm_x4(al[i], Al + SWZ128(off));
            }
#pragma unroll
            for (int tt = 0; tt < 4; tt++) {
                uint32_t bh[4], bl[4];
                uint32_t off = b_row0 + (uint32_t)(tt * 16 * 128) + (uint32_t)(kc * 2) + b_kb;
                ldsm_x4(bh, Bh + SWZ128(off));
                ldsm_x4(bl, Bl + SWZ128(off));
#pragma unroll
                for (int i = 0; i < 2; i++) {
                    mma_bf16(acc[i][2 * tt],     ah[i], bh);
                    mma_bf16(acc[i][2 * tt + 1], ah[i], bh + 2);
                    mma_bf16(acc[i][2 * tt],     al[i], bh);
                    mma_bf16(acc[i][2 * tt + 1], al[i], bh + 2);
                    mma_bf16(acc[i][2 * tt],     ah[i], bl);
                    mma_bf16(acc[i][2 * tt + 1], ah[i], bl + 2);
                }
            }
        }
        __syncthreads();
    }

    const int col0 = wn * 64 + (lane & 3) * 2;
    const int rbase = wm * 32 + (lane >> 2);
#pragma unroll
    for (int i = 0; i < 2; i++) {
        int m0 = rbase + i * 16;
#pragma unroll
        for (int half = 0; half < 2; half++) {
            int m = m0 + half * 8;
            if (m < NMASK) {
                float bias = conv_b[m];
                size_t base = ((size_t)(b * NMASK + m) << 14) + (h << 7);
#pragma unroll
                for (int j = 0; j < 8; j++) {
                    float2 v;
                    v.x = acc[i][j][half * 2 + 0] + bias;
                    v.y = acc[i][j][half * 2 + 1] + bias;
                    *(float2*)&iam_out[base + col0 + j * 8] = v;
                }
            }
        }
    }
}

// ---------------- softmax over HW per (b,n) row -> bf16 hi/lo prob ------------
__global__ __launch_bounds__(256)
void softmax_kernel(const float* __restrict__ iam) {
    const int row = blockIdx.x;
    const float* x = iam + ((size_t)row << 14);
    __nv_bfloat16* ph = g_phi + ((size_t)row << 14);
    __nv_bfloat16* pl = g_plo + ((size_t)row << 14);
    const int tid = threadIdx.x;
    __shared__ float red[256];

    float mx = -1e30f;
    for (int i = tid; i < HW; i += 256) mx = fmaxf(mx, x[i]);
    red[tid] = mx; __syncthreads();
    for (int s = 128; s > 0; s >>= 1) {
        if (tid < s) red[tid] = fmaxf(red[tid], red[tid + s]);
        __syncthreads();
    }
    const float M = red[0];
    __syncthreads();

    float sum = 0.f;
    for (int i = tid; i < HW; i += 256) sum += __expf(x[i] - M);
    red[tid] = sum; __syncthreads();
    for (int s = 128; s > 0; s >>= 1) {
        if (tid < s) red[tid] += red[tid + s];
        __syncthreads();
    }
    const float inv = 1.f / red[0];

    for (int i = tid; i < HW; i += 256) {
        float p = __expf(x[i] - M) * inv;
        __nv_bfloat16 hi = __float2bfloat16(p);
        ph[i] = hi;
        pl[i] = __float2bfloat16(p - __bfloat162float(hi));
    }
}

// ---------------- pooling via ldmatrix + mma.sync (same micro-kernel) ---------
// grid (32 ksplit, 2 c-half, 8 b). A = prob [n][k], B = feat [c][k]. Kc = 512.
__global__ __launch_bounds__(256, 2)
void pool_mma_kernel() {
    extern __shared__ char smem[];
    const uint32_t sb = smem_u32(smem);
    const uint32_t tile0 = (sb + 1023) & ~1023u;
    char* tb = smem + (tile0 - sb);
    const uint32_t Ah = tile0, Al = tile0 + 16384, Bh = tile0 + 32768, Bl = tile0 + 49152;

    const int ks = blockIdx.x, ct = blockIdx.y, b = blockIdx.z;
    const int p0 = ks * (HW / POOL_KSPLIT);          // k chunk base, 512-aligned
    const int tid = threadIdx.x;
    const int wid = tid >> 5, lane = tid & 31;
    const int wm = wid >> 1, wn = wid & 1;

    const int lmat = lane >> 3, lrow = lane & 7;
    const uint32_t a_row0 = (uint32_t)((wm * 32 + (lmat & 1) * 8 + lrow) * 128);
    const uint32_t a_kb   = (uint32_t)((lmat >> 1) * 16);
    const uint32_t b_row0 = (uint32_t)((wn * 64 + (lmat >> 1) * 8 + lrow) * 128);
    const uint32_t b_kb   = (uint32_t)((lmat & 1) * 16);

    const __nv_bfloat16* phi = g_phi + ((size_t)(b * NMASK) << 14);
    const __nv_bfloat16* plo = g_plo + ((size_t)(b * NMASK) << 14);
    const __nv_bfloat16* fhi = g_fChi + ((size_t)b * C_DIM) * HW;
    const __nv_bfloat16* flo = g_fClo + ((size_t)b * C_DIM) * HW;

    float acc[2][8][4];
#pragma unroll
    for (int i = 0; i < 2; i++)
#pragma unroll
        for (int j = 0; j < 8; j++)
#pragma unroll
            for (int v = 0; v < 4; v++) acc[i][j][v] = 0.f;

    for (int q = 0; q < 8; q++) {                    // 8 x 64 = 512 k per CTA
        const int kk0 = p0 + q * CHUNK_K;
        // A: prob rows (n), guarded n<NMASK
#pragma unroll
        for (int i = 0; i < 4; i++) {
            int idx = tid + i * 256;
            int n = idx >> 3, g = idx & 7;
            uint4 vh = make_uint4(0, 0, 0, 0), vl = make_uint4(0, 0, 0, 0);
            if (n < NMASK) {
                size_t off = ((size_t)n << 14) + kk0 + g * 8;
                vh = *(const uint4*)(phi + off);
                vl = *(const uint4*)(plo + off);
            }
            uint32_t so = SWZ128((uint32_t)(n * 128 + g * 16));
            *(uint4*)(tb + so)          = vh;
            *(uint4*)(tb + 16384 + so)  = vl;
        }
        // B: feat c-rows
#pragma unroll
        for (int i = 0; i < 4; i++) {
            int idx = tid + i * 256;
            int cc = idx >> 3, g = idx & 7;
            size_t off = ((size_t)(ct * 128 + cc)) * HW + kk0 + g * 8;
            uint32_t so = SWZ128((uint32_t)(cc * 128 + g * 16));
            *(uint4*)(tb + 32768 + so) = *(const uint4*)(fhi + off);
            *(uint4*)(tb + 49152 + so) = *(const uint4*)(flo + off);
        }
        __syncthreads();

#pragma unroll
        for (int kc = 0; kc < CHUNK_K; kc += 16) {
            uint32_t ah[2][4], al[2][4];
#pragma unroll
            for (int i = 0; i < 2; i++) {
                uint32_t off = a_row0 + (uint32_t)(i * 16 * 128) + (uint32_t)(kc * 2) + a_kb;
                ldsm_x4(ah[i], Ah + SWZ128(off));
                ldsm_x4(al[i], Al + SWZ128(off));
            }
#pragma unroll
            for (int tt = 0; tt < 4; tt++) {
                uint32_t bh[4], bl[4];
                uint32_t off = b_row0 + (uint32_t)(tt * 16 * 128) + (uint32_t)(kc * 2) + b_kb;
                ldsm_x4(bh, Bh + SWZ128(off));
                ldsm_x4(bl, Bl + SWZ128(off));
#pragma unroll
                for (int i = 0; i < 2; i++) {
                    mma_bf16(acc[i][2 * tt],     ah[i], bh);
                    mma_bf16(acc[i][2 * tt + 1], ah[i], bh + 2);
                    mma_bf16(acc[i][2 * tt],     al[i], bh);
                    mma_bf16(acc[i][2 * tt + 1], al[i], bh + 2);
                    mma_bf16(acc[i][2 * tt],     ah[i], bl);
                    mma_bf16(acc[i][2 * tt + 1], ah[i], bl + 2);
                }
            }
        }
        __syncthreads();
    }

    // epilogue: partials into g_part (fc layout unchanged)
    const int col0 = wn * 64 + (lane & 3) * 2;
    const int rbase = wm * 32 + (lane >> 2);
#pragma unroll
    for (int i = 0; i < 2; i++) {
        int m0 = rbase + i * 16;
#pragma unroll
        for (int half = 0; half < 2; half++) {
            int n = m0 + half * 8;
            if (n < NMASK) {
                size_t base = (size_t)ks * (NROWS * C_DIM)
                            + (size_t)(b * NMASK + n) * C_DIM + ct * 128;
#pragma unroll
                for (int j = 0; j < 8; j++) {
                    float2 v;
                    v.x = acc[i][j][half * 2 + 0];
                    v.y = acc[i][j][half * 2 + 1];
                    *(float2*)&g_part[base + col0 + j * 8] = v;
                }
            }
        }
    }
}

// ---------------- fc: inst2 = relu( (sum_k part) @ fc_w^T + fc_b ) ------------
__global__ __launch_bounds__(256)
void fc_kernel(const float* __restrict__ fc_b) {
    const int r0 = blockIdx.x * 8;
    __shared__ float s_in[8][C_DIM];
    const int tid = threadIdx.x;

#pragma unroll
    for (int rr = 0; rr < 8; rr++) {
        float v = 0.f;
#pragma unroll
        for (int ks = 0; ks < POOL_KSPLIT; ks++)
            v += g_part[(size_t)ks * (NROWS * C_DIM) + (r0 + rr) * C_DIM + tid];
        s_in[rr][tid] = v;
    }
    __syncthreads();

    const float bias = fc_b[tid];
    float acc[8];
#pragma unroll
    for (int rr = 0; rr < 8; rr++) acc[rr] = bias;
    for (int c = 0; c < C_DIM; c++) {
        float w = g_fcT[c * C_DIM + tid];
#pragma unroll
        for (int rr = 0; rr < 8; rr++) acc[rr] += s_in[rr][c] * w;
    }
#pragma unroll
    for (int rr = 0; rr < 8; rr++)
        g_inst2[(r0 + rr) * C_DIM + tid] = fmaxf(acc[rr], 0.f);
}

// ---------------- heads ----------------
__global__ __launch_bounds__(192)
void heads_kernel(float* __restrict__ out,
                  const float* __restrict__ cls_w, const float* __restrict__ cls_b,
                  const float* __restrict__ obj_w, const float* __restrict__ obj_b,
                  const float* __restrict__ mk_b) {
    const int r = blockIdx.x;
    __shared__ float s[C_DIM];
    const int tid = threadIdx.x;
    for (int i = tid; i < C_DIM; i += 192) s[i] = g_inst2[r * C_DIM + i];
    __syncthreads();

    if (tid < 128) {
        float a = mk_b[tid];
        for (int c = 0; c < C_DIM; c++) a += s[c] * g_mkT[c * 128 + tid];
        out[800 + r * 128 + tid] = a;
    } else {
        const int w = (tid - 128) >> 5;
        const int lane = tid & 31;
        const float* wv = (w == 0) ? cls_w : obj_w;
        float p = 0.f;
        for (int c = lane; c < C_DIM; c += 32) p += s[c] * wv[c];
#pragma unroll
        for (int off = 16; off; off >>= 1) p += __shfl_down_sync(0xffffffff, p, off);
        if (lane == 0) {
            if (w == 0) out[r] = p + cls_b[0];
            else        out[103200 + r] = p + obj_b[0];
        }
    }
}

// ---------------- launch ----------------
// d_out layout (float): [0,800) pred_logits | [800,103200) pred_kernel
//                       | [103200,104000) pred_scores | [104000, ...) iam
extern "C" void kernel_launch(void* const* d_in, const int* in_sizes, int n_in,
                              void* d_out, int out_size) {
    const float* features = (const float*)d_in[0];
    const float* conv_w   = (const float*)d_in[1];
    const float* conv_b   = (const float*)d_in[2];
    const float* fc_w     = (const float*)d_in[4];
    const float* fc_b     = (const float*)d_in[5];
    const float* cls_w    = (const float*)d_in[6];
    const float* cls_b    = (const float*)d_in[7];
    const float* mk_w     = (const float*)d_in[8];
    const float* mk_b     = (const float*)d_in[9];
    const float* obj_w    = (const float*)d_in[10];
    const float* obj_b    = (const float*)d_in[11];
    float* out = (float*)d_out;
    float* iam = out + 104000;

    cudaFuncSetAttribute(conv_mma_kernel,
                         cudaFuncAttributeMaxDynamicSharedMemorySize, CONV_SMEM);
    cudaFuncSetAttribute(pool_mma_kernel,
                         cudaFuncAttributeMaxDynamicSharedMemorySize, CONV_SMEM);

    prep_w_kernel<<<1152, 256>>>(conv_w, fc_w, mk_w);
    prep_feat_kernel<<<dim3(256, 4, 8), 256>>>(features);
    conv_mma_kernel<<<dim3(HDIM, 8), 256, CONV_SMEM>>>(conv_b, iam);
    softmax_kernel<<<NROWS, 256>>>(iam);
    pool_mma_kernel<<<dim3(POOL_KSPLIT, 2, 8), 256, CONV_SMEM>>>();
    fc_kernel<<<100, 256>>>(fc_b);
    heads_kernel<<<NROWS, 192>>>(out, cls_w, cls_b, obj_w, obj_b, mk_b);
}